// round 11
// baseline (speedup 1.0000x reference)
#include <cuda_runtime.h>

#define Bd 8
#define Nd 2048
#define F_IN 256
#define F_OUT 64
#define ALPHA 0.2f

#define TI 64
#define TJ 64
#define SPLIT 4
#define JPB (Nd / SPLIT)   // 512 j's per block
#define PST 68             // smem row stride (floats), 16B-aligned

typedef unsigned long long ull;

// ---- packed f32x2 helpers (sm_103a FFMA2: 2x fp32 FMA throughput) ----
__device__ __forceinline__ void fma2(ull& d, ull a, ull b) {
    asm("fma.rn.f32x2 %0, %1, %2, %0;" : "+l"(d) : "l"(a), "l"(b));
}
__device__ __forceinline__ ull pack2(float x) {
    ull r; asm("mov.b64 %0, {%1, %1};" : "=l"(r) : "f"(x)); return r;
}
__device__ __forceinline__ void unpack2(float& lo, float& hi, ull v) {
    asm("mov.b64 {%0, %1}, %2;" : "=f"(lo), "=f"(hi) : "l"(v));
}

// ---- scratch (__device__ globals; allocation-free rule) ----
__device__ __align__(16) float g_Wh[Bd * Nd * F_OUT];            // 4 MB
__device__ __align__(16) float g_es[Bd * Nd];
__device__ __align__(16) float g_ed[Bd * Nd];
__device__ __align__(16) float g_pacc[SPLIT * Bd * Nd * F_OUT];  // 16 MB partials
__device__ __align__(16) float g_prs[SPLIT * Bd * Nd];           // partial rowsums

// ---------------------------------------------------------------------------
// Kernel 1: Wh = h @ W, e_src = Wh.a1, e_dst = Wh.a2.
// Occupancy-first layout: 32 rows per block -> 512 blocks (3.5/SM vs 1.7
// before). Thread = (row, 8-col group): 4 independent FFMA2 chains, K staged
// in chunks of 64 (only 8 barriers total).
// ---------------------------------------------------------------------------
__global__ __launch_bounds__(256) void wh_kernel(const float* __restrict__ h,
                                                 const float* __restrict__ W,
                                                 const float* __restrict__ a) {
    __shared__ float hs[32][68];   // 32 rows x 64-k chunk (pad 4)
    __shared__ float Ws[64][72];   // 64-k chunk x 64 cols (pad 8)

    int t    = threadIdx.x;
    int row0 = blockIdx.x * 32;
    int r    = t >> 3;             // local row 0..31
    int colg = t & 7;              // 8 col-groups of 8 cols

    const float4* h4 = (const float4*)h;   // [row][64]
    const float4* W4 = (const float4*)W;   // [F_IN][16]

    ull acc[4] = {};               // 8 cols as 4 f32x2 pairs

    for (int c = 0; c < 4; c++) {  // F_IN in chunks of 64
        __syncthreads();
#pragma unroll
        for (int q = 0; q < 2; q++) {      // stage h chunk: 512 float4
            int idx = t * 2 + q;
            int rr = idx >> 4, kq = idx & 15;
            *(float4*)&hs[rr][kq * 4] = h4[(size_t)(row0 + rr) * 64 + c * 16 + kq];
        }
#pragma unroll
        for (int q = 0; q < 4; q++) {      // stage W chunk: 1024 float4
            int idx = t * 4 + q;
            int k = idx >> 4, cq = idx & 15;
            *(float4*)&Ws[k][cq * 4] = W4[(size_t)(c * 64 + k) * 16 + cq];
        }
        __syncthreads();
#pragma unroll 16
        for (int k = 0; k < 64; k++) {
            ull hp = pack2(hs[r][k]);
            ulonglong2 w0 = *(const ulonglong2*)&Ws[k][colg * 8];
            ulonglong2 w1 = *(const ulonglong2*)&Ws[k][colg * 8 + 4];
            fma2(acc[0], hp, w0.x); fma2(acc[1], hp, w0.y);
            fma2(acc[2], hp, w1.x); fma2(acc[3], hp, w1.y);
        }
    }

    int row = row0 + r;
    float w[8];
    unpack2(w[0], w[1], acc[0]); unpack2(w[2], w[3], acc[1]);
    unpack2(w[4], w[5], acc[2]); unpack2(w[6], w[7], acc[3]);
    *(float4*)(g_Wh + (size_t)row * F_OUT + colg * 8)     = make_float4(w[0], w[1], w[2], w[3]);
    *(float4*)(g_Wh + (size_t)row * F_OUT + colg * 8 + 4) = make_float4(w[4], w[5], w[6], w[7]);

    // attention logits: dot with a1/a2 over this thread's 8 cols, then
    // reduce across the 8 col-groups (8 consecutive lanes share a row).
    float p = 0.f, q = 0.f;
#pragma unroll
    for (int u = 0; u < 2; u++) {
        float4 v1 = ((const float4*)a)[colg * 2 + u];
        float4 v2 = ((const float4*)a)[16 + colg * 2 + u];
        p += w[u*4+0]*v1.x + w[u*4+1]*v1.y + w[u*4+2]*v1.z + w[u*4+3]*v1.w;
        q += w[u*4+0]*v2.x + w[u*4+1]*v2.y + w[u*4+2]*v2.z + w[u*4+3]*v2.w;
    }
#pragma unroll
    for (int off = 4; off > 0; off >>= 1) {
        p += __shfl_xor_sync(0xFFFFFFFFu, p, off);
        q += __shfl_xor_sync(0xFFFFFFFFu, q, off);
    }
    if (colg == 0) {
        g_es[row] = p;
        g_ed[row] = q;
    }
}

// ---------------------------------------------------------------------------
// Kernel 2: fused attention + aggregation, split-K over j (4-way: 1024
// blocks was measurably better than 512 in R8/R9 A-B). P tile stored
// TRANSPOSED+swizzled in smem so both GEMM operands are LDS.128; 4x4
// micro-tile via FFMA2. adj tile for the NEXT j0 prefetched into registers
// so the GEMM covers the ~600cyc DRAM latency.
// Softmax needs no max-subtraction: scores bounded ~10.
// ---------------------------------------------------------------------------
__global__ __launch_bounds__(256, 4) void gat_kernel(const int* __restrict__ adj) {
    __shared__ float PsT[TJ][PST];
    __shared__ float Whs[TJ][PST];
    __shared__ float es_s[TI];
    __shared__ float ed_s[TJ];
    __shared__ float rowsum[TI];

    int t     = threadIdx.x;
    int b     = blockIdx.y;
    int i0    = blockIdx.x * TI;
    int split = blockIdx.z;
    int jbase = split * JPB;
    int jend  = jbase + JPB;

    if (t < TI) rowsum[t] = 0.f;
    if (t < 16) ((float4*)es_s)[t] = ((const float4*)(g_es + (size_t)b * Nd + i0))[t];
    __syncthreads();

    int pi = t >> 2;
    int jq = t & 3;
    float esi = es_s[pi];

    int ty = t >> 4;
    int tx = t & 15;
    ull acc[4][2] = {};

    const float* Whb  = g_Wh + (size_t)b * Nd * F_OUT;
    const float* edb  = g_ed + (size_t)b * Nd;
    const int4*  arow = (const int4*)(adj + (size_t)b * Nd * Nd + (size_t)(i0 + pi) * Nd);

    int lr = t >> 2;
    int lp = t & 3;

    // prefetch adj for the first tile
    int4 av[4];
#pragma unroll
    for (int q = 0; q < 4; q++) av[q] = arow[(jbase >> 2) + jq * 4 + q];

    for (int j0 = jbase; j0 < jend; j0 += TJ) {
        __syncthreads();   // previous GEMM done with PsT/Whs/ed_s

        {   // stage Wh tile + ed tile
            const float4* src = (const float4*)(Whb + (size_t)(j0 + lr) * F_OUT);
            float4* dst = (float4*)&Whs[lr][0];
#pragma unroll
            for (int q = 0; q < 4; q++) dst[lp * 4 + q] = src[lp * 4 + q];
            if (t < 16) ((float4*)ed_s)[t] = ((const float4*)(edb + j0))[t];
        }
        __syncthreads();

        // P tile (transposed+swizzled) + partial row sums, from prefetched av
        float psum = 0.f;
#pragma unroll
        for (int q = 0; q < 4; q++) {
            int4 a4 = av[q];
            int jb  = jq * 16 + q * 4;
            int col = pi ^ jb;
            float e, p0, p1, p2, p3;
            e = esi + ed_s[jb + 0]; e = (e > 0.f) ? e : ALPHA * e; p0 = a4.x ? __expf(e) : 0.f;
            e = esi + ed_s[jb + 1]; e = (e > 0.f) ? e : ALPHA * e; p1 = a4.y ? __expf(e) : 0.f;
            e = esi + ed_s[jb + 2]; e = (e > 0.f) ? e : ALPHA * e; p2 = a4.z ? __expf(e) : 0.f;
            e = esi + ed_s[jb + 3]; e = (e > 0.f) ? e : ALPHA * e; p3 = a4.w ? __expf(e) : 0.f;
            psum += p0 + p1 + p2 + p3;
            PsT[jb + 0][col] = p0;
            PsT[jb + 1][col] = p1;
            PsT[jb + 2][col] = p2;
            PsT[jb + 3][col] = p3;
        }
        // prefetch adj for next tile (wrap to jbase on last iter; harmless)
        {
            int jn = (j0 + TJ < jend) ? j0 + TJ : jbase;
#pragma unroll
            for (int q = 0; q < 4; q++) av[q] = arow[(jn >> 2) + jq * 4 + q];
        }
        psum += __shfl_xor_sync(0xFFFFFFFFu, psum, 1);
        psum += __shfl_xor_sync(0xFFFFFFFFu, psum, 2);
        if (jq == 0) rowsum[pi] += psum;
        __syncthreads();

        // acc += P @ Whs  (64x64x64), all-LDS.128 + FFMA2
#pragma unroll 16
        for (int k = 0; k < TJ; k++) {
            float4 pv = *(const float4*)&PsT[k][(ty * 4) ^ (k & 0x3C)];
            ulonglong2 bv = *(const ulonglong2*)&Whs[k][tx * 4];
            ull a0 = pack2(pv.x), a1 = pack2(pv.y), a2 = pack2(pv.z), a3 = pack2(pv.w);
            fma2(acc[0][0], a0, bv.x); fma2(acc[0][1], a0, bv.y);
            fma2(acc[1][0], a1, bv.x); fma2(acc[1][1], a1, bv.y);
            fma2(acc[2][0], a2, bv.x); fma2(acc[2][1], a2, bv.y);
            fma2(acc[3][0], a3, bv.x); fma2(acc[3][1], a3, bv.y);
        }
    }
    __syncthreads();

    // write unnormalized partials + partial rowsums
    float* pacc = g_pacc + (((size_t)split * Bd + b) * Nd + i0) * F_OUT;
#pragma unroll
    for (int m = 0; m < 4; m++) {
        float4 o;
        unpack2(o.x, o.y, acc[m][0]);
        unpack2(o.z, o.w, acc[m][1]);
        *(float4*)(pacc + (size_t)(ty * 4 + m) * F_OUT + tx * 4) = o;
    }
    if (t < TI) g_prs[((size_t)split * Bd + b) * Nd + i0 + t] = rowsum[t];
}

// ---------------------------------------------------------------------------
// Kernel 3: sum the split partials, normalize, ELU, store.
// ---------------------------------------------------------------------------
__global__ __launch_bounds__(256) void reduce_kernel(float* __restrict__ out) {
    int tid = blockIdx.x * 256 + threadIdx.x;   // 0 .. B*N*16-1
    int row = tid >> 4;                          // b*N + i
    int c4  = tid & 15;

    float4 s = make_float4(0.f, 0.f, 0.f, 0.f);
    float rs = 0.f;
#pragma unroll
    for (int sp = 0; sp < SPLIT; sp++) {
        float4 v = *(const float4*)(g_pacc + ((size_t)sp * Bd * Nd + row) * F_OUT + c4 * 4);
        s.x += v.x; s.y += v.y; s.z += v.z; s.w += v.w;
        rs += g_prs[(size_t)sp * Bd * Nd + row];
    }
    float inv = 1.0f / rs;
    float4 o; float v;
    v = s.x * inv; o.x = (v > 0.f) ? v : expm1f(v);
    v = s.y * inv; o.y = (v > 0.f) ? v : expm1f(v);
    v = s.z * inv; o.z = (v > 0.f) ? v : expm1f(v);
    v = s.w * inv; o.w = (v > 0.f) ? v : expm1f(v);
    *(float4*)(out + (size_t)row * F_OUT + c4 * 4) = o;
}

// ---------------------------------------------------------------------------
extern "C" void kernel_launch(void* const* d_in, const int* in_sizes, int n_in,
                              void* d_out, int out_size) {
    const float* h   = (const float*)d_in[0];   // (8,2048,256) f32
    const int*   adj = (const int*)d_in[1];     // (8,2048,2048) i32
    const float* W   = (const float*)d_in[2];   // (256,64) f32
    const float* a   = (const float*)d_in[3];   // (128,1) f32
    float* out = (float*)d_out;                 // (8,2048,64) f32

    wh_kernel<<<Bd * Nd / 32, 256>>>(h, W, a);
    dim3 grid(Nd / TI, Bd, SPLIT);
    gat_kernel<<<grid, 256>>>(adj);
    reduce_kernel<<<Bd * Nd * 16 / 256, 256>>>(out);
}

// round 12
// speedup vs baseline: 1.1492x; 1.1492x over previous
#include <cuda_runtime.h>

#define Bd 8
#define Nd 2048
#define F_IN 256
#define F_OUT 64
#define ALPHA 0.2f

#define TI 64
#define TJ 64
#define SPLIT 4
#define JPB (Nd / SPLIT)   // 512 j's per block
#define PST 68             // smem row stride (floats), 16B-aligned

typedef unsigned long long ull;

// ---- packed f32x2 helpers (sm_103a FFMA2: 2x fp32 FMA throughput) ----
__device__ __forceinline__ void fma2(ull& d, ull a, ull b) {
    asm("fma.rn.f32x2 %0, %1, %2, %0;" : "+l"(d) : "l"(a), "l"(b));
}
__device__ __forceinline__ ull pack2(float x) {
    ull r; asm("mov.b64 %0, {%1, %1};" : "=l"(r) : "f"(x)); return r;
}
__device__ __forceinline__ void unpack2(float& lo, float& hi, ull v) {
    asm("mov.b64 {%0, %1}, %2;" : "=f"(lo), "=f"(hi) : "l"(v));
}

// ---- scratch (__device__ globals; allocation-free rule) ----
__device__ __align__(16) float g_Wh[Bd * Nd * F_OUT];            // 4 MB
__device__ __align__(16) float g_es[Bd * Nd];
__device__ __align__(16) float g_ed[Bd * Nd];
__device__ __align__(16) float g_pacc[SPLIT * Bd * Nd * F_OUT];  // 16 MB partials
__device__ __align__(16) float g_prs[SPLIT * Bd * Nd];           // partial rowsums

// ---------------------------------------------------------------------------
// Kernel 1: Wh = h @ W, e_src = Wh.a1, e_dst = Wh.a2.
// 2x8 microtile (best measured LDS-per-FLOP config) on SMALL blocks:
// 32 rows x 64 cols, 128 threads -> 512 blocks, ~8 resident blocks/SM
// (regs ~56) = ~32 warps/SM for latency hiding. K staged in chunks of 32.
// ---------------------------------------------------------------------------
__global__ __launch_bounds__(128) void wh_kernel(const float* __restrict__ h,
                                                 const float* __restrict__ W,
                                                 const float* __restrict__ a) {
    __shared__ float hs[32][36];   // 32 rows x 32-k chunk (pad 4)
    __shared__ float Ws[32][72];   // 32-k chunk x 64 cols (pad 8)

    int t    = threadIdx.x;        // 0..127
    int row0 = blockIdx.x * 32;
    int colg = t & 7;              // 8 col-groups of 8 cols
    int rp   = t >> 3;             // 0..15 -> rows rp*2, rp*2+1

    const float4* h4 = (const float4*)h;   // [row][64]
    const float4* W4 = (const float4*)W;   // [F_IN][16]

    ull acc[2][4] = {};            // 2 rows x 8 cols (4 f32x2 pairs each)

    for (int c = 0; c < 8; c++) {  // F_IN in chunks of 32
        __syncthreads();
#pragma unroll
        for (int q = 0; q < 2; q++) {      // stage h chunk: 256 float4
            int idx = t * 2 + q;
            int r = idx >> 3, kq = idx & 7;
            *(float4*)&hs[r][kq * 4] = h4[(size_t)(row0 + r) * 64 + c * 8 + kq];
        }
#pragma unroll
        for (int q = 0; q < 4; q++) {      // stage W chunk: 512 float4
            int idx = t * 4 + q;
            int k = idx >> 4, cq = idx & 15;
            *(float4*)&Ws[k][cq * 4] = W4[(size_t)(c * 32 + k) * 16 + cq];
        }
        __syncthreads();
#pragma unroll
        for (int k = 0; k < 32; k++) {
            ulonglong2 w0 = *(const ulonglong2*)&Ws[k][colg * 8];
            ulonglong2 w1 = *(const ulonglong2*)&Ws[k][colg * 8 + 4];
            ull hp0 = pack2(hs[rp * 2 + 0][k]);
            ull hp1 = pack2(hs[rp * 2 + 1][k]);
            fma2(acc[0][0], hp0, w0.x); fma2(acc[0][1], hp0, w0.y);
            fma2(acc[0][2], hp0, w1.x); fma2(acc[0][3], hp0, w1.y);
            fma2(acc[1][0], hp1, w0.x); fma2(acc[1][1], hp1, w0.y);
            fma2(acc[1][2], hp1, w1.x); fma2(acc[1][3], hp1, w1.y);
        }
    }

    // a-vector slices for this col-group
    float a1s[8], a2s[8];
#pragma unroll
    for (int q = 0; q < 2; q++) {
        float4 v1 = ((const float4*)a)[colg * 2 + q];
        float4 v2 = ((const float4*)a)[16 + colg * 2 + q];
        a1s[q * 4 + 0] = v1.x; a1s[q * 4 + 1] = v1.y; a1s[q * 4 + 2] = v1.z; a1s[q * 4 + 3] = v1.w;
        a2s[q * 4 + 0] = v2.x; a2s[q * 4 + 1] = v2.y; a2s[q * 4 + 2] = v2.z; a2s[q * 4 + 3] = v2.w;
    }

#pragma unroll
    for (int m = 0; m < 2; m++) {
        int row = row0 + rp * 2 + m;
        float w[8];
        unpack2(w[0], w[1], acc[m][0]); unpack2(w[2], w[3], acc[m][1]);
        unpack2(w[4], w[5], acc[m][2]); unpack2(w[6], w[7], acc[m][3]);
        *(float4*)(g_Wh + (size_t)row * F_OUT + colg * 8)     = make_float4(w[0], w[1], w[2], w[3]);
        *(float4*)(g_Wh + (size_t)row * F_OUT + colg * 8 + 4) = make_float4(w[4], w[5], w[6], w[7]);

        float p = 0.f, q = 0.f;
#pragma unroll
        for (int u = 0; u < 8; u++) { p += w[u] * a1s[u]; q += w[u] * a2s[u]; }
        // reduce over the 8 col-groups (8 consecutive lanes share a row pair)
#pragma unroll
        for (int off = 4; off > 0; off >>= 1) {
            p += __shfl_xor_sync(0xFFFFFFFFu, p, off);
            q += __shfl_xor_sync(0xFFFFFFFFu, q, off);
        }
        if (colg == 0) {
            g_es[row] = p;
            g_ed[row] = q;
        }
    }
}

// ---------------------------------------------------------------------------
// Kernel 2: fused attention + aggregation, split-K over j (4-way; 1024
// blocks measured best). P tile stored TRANSPOSED+swizzled in smem so both
// GEMM operands are LDS.128; 4x4 micro-tile via FFMA2. adj tile for the
// NEXT j0 prefetched into registers. No max-subtraction needed: scores
// bounded ~10 so exp() stays finite in fp32.
// ---------------------------------------------------------------------------
__global__ __launch_bounds__(256, 4) void gat_kernel(const int* __restrict__ adj) {
    __shared__ float PsT[TJ][PST];
    __shared__ float Whs[TJ][PST];
    __shared__ float es_s[TI];
    __shared__ float ed_s[TJ];
    __shared__ float rowsum[TI];

    int t     = threadIdx.x;
    int b     = blockIdx.y;
    int i0    = blockIdx.x * TI;
    int split = blockIdx.z;
    int jbase = split * JPB;
    int jend  = jbase + JPB;

    if (t < TI) rowsum[t] = 0.f;
    if (t < 16) ((float4*)es_s)[t] = ((const float4*)(g_es + (size_t)b * Nd + i0))[t];
    __syncthreads();

    int pi = t >> 2;
    int jq = t & 3;
    float esi = es_s[pi];

    int ty = t >> 4;
    int tx = t & 15;
    ull acc[4][2] = {};

    const float* Whb  = g_Wh + (size_t)b * Nd * F_OUT;
    const float* edb  = g_ed + (size_t)b * Nd;
    const int4*  arow = (const int4*)(adj + (size_t)b * Nd * Nd + (size_t)(i0 + pi) * Nd);

    int lr = t >> 2;
    int lp = t & 3;

    // prefetch adj for the first tile
    int4 av[4];
#pragma unroll
    for (int q = 0; q < 4; q++) av[q] = arow[(jbase >> 2) + jq * 4 + q];

    for (int j0 = jbase; j0 < jend; j0 += TJ) {
        __syncthreads();   // previous GEMM done with PsT/Whs/ed_s

        {   // stage Wh tile + ed tile
            const float4* src = (const float4*)(Whb + (size_t)(j0 + lr) * F_OUT);
            float4* dst = (float4*)&Whs[lr][0];
#pragma unroll
            for (int q = 0; q < 4; q++) dst[lp * 4 + q] = src[lp * 4 + q];
            if (t < 16) ((float4*)ed_s)[t] = ((const float4*)(edb + j0))[t];
        }
        __syncthreads();

        // P tile (transposed+swizzled) + partial row sums, from prefetched av
        float psum = 0.f;
#pragma unroll
        for (int q = 0; q < 4; q++) {
            int4 a4 = av[q];
            int jb  = jq * 16 + q * 4;
            int col = pi ^ jb;
            float e, p0, p1, p2, p3;
            e = esi + ed_s[jb + 0]; e = (e > 0.f) ? e : ALPHA * e; p0 = a4.x ? __expf(e) : 0.f;
            e = esi + ed_s[jb + 1]; e = (e > 0.f) ? e : ALPHA * e; p1 = a4.y ? __expf(e) : 0.f;
            e = esi + ed_s[jb + 2]; e = (e > 0.f) ? e : ALPHA * e; p2 = a4.z ? __expf(e) : 0.f;
            e = esi + ed_s[jb + 3]; e = (e > 0.f) ? e : ALPHA * e; p3 = a4.w ? __expf(e) : 0.f;
            psum += p0 + p1 + p2 + p3;
            PsT[jb + 0][col] = p0;
            PsT[jb + 1][col] = p1;
            PsT[jb + 2][col] = p2;
            PsT[jb + 3][col] = p3;
        }
        // prefetch adj for next tile (wrap to jbase on last iter; harmless)
        {
            int jn = (j0 + TJ < jend) ? j0 + TJ : jbase;
#pragma unroll
            for (int q = 0; q < 4; q++) av[q] = arow[(jn >> 2) + jq * 4 + q];
        }
        psum += __shfl_xor_sync(0xFFFFFFFFu, psum, 1);
        psum += __shfl_xor_sync(0xFFFFFFFFu, psum, 2);
        if (jq == 0) rowsum[pi] += psum;
        __syncthreads();

        // acc += P @ Whs  (64x64x64), all-LDS.128 + FFMA2
#pragma unroll 16
        for (int k = 0; k < TJ; k++) {
            float4 pv = *(const float4*)&PsT[k][(ty * 4) ^ (k & 0x3C)];
            ulonglong2 bv = *(const ulonglong2*)&Whs[k][tx * 4];
            ull a0 = pack2(pv.x), a1 = pack2(pv.y), a2 = pack2(pv.z), a3 = pack2(pv.w);
            fma2(acc[0][0], a0, bv.x); fma2(acc[0][1], a0, bv.y);
            fma2(acc[1][0], a1, bv.x); fma2(acc[1][1], a1, bv.y);
            fma2(acc[2][0], a2, bv.x); fma2(acc[2][1], a2, bv.y);
            fma2(acc[3][0], a3, bv.x); fma2(acc[3][1], a3, bv.y);
        }
    }
    __syncthreads();

    // write unnormalized partials + partial rowsums
    float* pacc = g_pacc + (((size_t)split * Bd + b) * Nd + i0) * F_OUT;
#pragma unroll
    for (int m = 0; m < 4; m++) {
        float4 o;
        unpack2(o.x, o.y, acc[m][0]);
        unpack2(o.z, o.w, acc[m][1]);
        *(float4*)(pacc + (size_t)(ty * 4 + m) * F_OUT + tx * 4) = o;
    }
    if (t < TI) g_prs[((size_t)split * Bd + b) * Nd + i0 + t] = rowsum[t];
}

// ---------------------------------------------------------------------------
// Kernel 3: sum the split partials, normalize, ELU, store.
// ---------------------------------------------------------------------------
__global__ __launch_bounds__(256) void reduce_kernel(float* __restrict__ out) {
    int tid = blockIdx.x * 256 + threadIdx.x;   // 0 .. B*N*16-1
    int row = tid >> 4;                          // b*N + i
    int c4  = tid & 15;

    float4 s = make_float4(0.f, 0.f, 0.f, 0.f);
    float rs = 0.f;
#pragma unroll
    for (int sp = 0; sp < SPLIT; sp++) {
        float4 v = *(const float4*)(g_pacc + ((size_t)sp * Bd * Nd + row) * F_OUT + c4 * 4);
        s.x += v.x; s.y += v.y; s.z += v.z; s.w += v.w;
        rs += g_prs[(size_t)sp * Bd * Nd + row];
    }
    float inv = 1.0f / rs;
    float4 o; float v;
    v = s.x * inv; o.x = (v > 0.f) ? v : expm1f(v);
    v = s.y * inv; o.y = (v > 0.f) ? v : expm1f(v);
    v = s.z * inv; o.z = (v > 0.f) ? v : expm1f(v);
    v = s.w * inv; o.w = (v > 0.f) ? v : expm1f(v);
    *(float4*)(out + (size_t)row * F_OUT + c4 * 4) = o;
}

// ---------------------------------------------------------------------------
extern "C" void kernel_launch(void* const* d_in, const int* in_sizes, int n_in,
                              void* d_out, int out_size) {
    const float* h   = (const float*)d_in[0];   // (8,2048,256) f32
    const int*   adj = (const int*)d_in[1];     // (8,2048,2048) i32
    const float* W   = (const float*)d_in[2];   // (256,64) f32
    const float* a   = (const float*)d_in[3];   // (128,1) f32
    float* out = (float*)d_out;                 // (8,2048,64) f32

    wh_kernel<<<Bd * Nd / 32, 128>>>(h, W, a);
    dim3 grid(Nd / TI, Bd, SPLIT);
    gat_kernel<<<grid, 256>>>(adj);
    reduce_kernel<<<Bd * Nd * 16 / 256, 256>>>(out);
}

// round 13
// speedup vs baseline: 1.1627x; 1.0117x over previous
#include <cuda_runtime.h>

#define Bd 8
#define Nd 2048
#define F_IN 256
#define F_OUT 64
#define ALPHA 0.2f

#define TI 64
#define TJ 64
#define SPLIT 4
#define JPB (Nd / SPLIT)   // 512 j's per block
#define PST 68             // smem row stride (floats), 16B-aligned
#define KSPLIT 4           // wh GEMM K-split (K=256 -> 64 per block)

typedef unsigned long long ull;

// ---- packed f32x2 helpers (sm_103a FFMA2: 2x fp32 FMA throughput) ----
__device__ __forceinline__ void fma2(ull& d, ull a, ull b) {
    asm("fma.rn.f32x2 %0, %1, %2, %0;" : "+l"(d) : "l"(a), "l"(b));
}
__device__ __forceinline__ ull pack2(float x) {
    ull r; asm("mov.b64 %0, {%1, %1};" : "=l"(r) : "f"(x)); return r;
}
__device__ __forceinline__ void unpack2(float& lo, float& hi, ull v) {
    asm("mov.b64 {%0, %1}, %2;" : "=f"(lo), "=f"(hi) : "l"(v));
}

// ---- scratch (__device__ globals; allocation-free rule) ----
__device__ __align__(16) float g_Wh[Bd * Nd * F_OUT];             // 4 MB
__device__ __align__(16) float g_whp[KSPLIT * Bd * Nd * F_OUT];   // 16 MB wh partials
__device__ __align__(16) float g_es[Bd * Nd];
__device__ __align__(16) float g_ed[Bd * Nd];
__device__ __align__(16) float g_pacc[SPLIT * Bd * Nd * F_OUT];   // 16 MB gat partials
__device__ __align__(16) float g_prs[SPLIT * Bd * Nd];            // partial rowsums

// ---------------------------------------------------------------------------
// Kernel 1a: Wh partials, split-K 4-way. Same 2x8 microtile as the best
// measured config, but grid = (512, 4) -> 8192 warps (was 2048: the R12
// profile showed the kernel was purely grid-starved at occ=21%).
// Each block: 32 rows x 64 cols x K-slice of 64.
// ---------------------------------------------------------------------------
__global__ __launch_bounds__(128) void wh_kernel(const float* __restrict__ h,
                                                 const float* __restrict__ W) {
    __shared__ float hs[32][36];   // 32 rows x 32-k chunk (pad 4)
    __shared__ float Ws[32][72];   // 32-k chunk x 64 cols (pad 8)

    int t     = threadIdx.x;       // 0..127
    int row0  = blockIdx.x * 32;
    int kbase = blockIdx.y * 64;   // this split's K range
    int colg  = t & 7;             // 8 col-groups of 8 cols
    int rp    = t >> 3;            // 0..15 -> rows rp*2, rp*2+1

    const float4* h4 = (const float4*)h;   // [row][64]
    const float4* W4 = (const float4*)W;   // [F_IN][16]

    ull acc[2][4] = {};            // 2 rows x 8 cols (4 f32x2 pairs each)

    for (int c = 0; c < 2; c++) {  // K-slice in chunks of 32
        __syncthreads();
#pragma unroll
        for (int q = 0; q < 2; q++) {      // stage h chunk: 256 float4
            int idx = t * 2 + q;
            int r = idx >> 3, kq = idx & 7;
            *(float4*)&hs[r][kq * 4] =
                h4[(size_t)(row0 + r) * 64 + (kbase >> 2) + c * 8 + kq];
        }
#pragma unroll
        for (int q = 0; q < 4; q++) {      // stage W chunk: 512 float4
            int idx = t * 4 + q;
            int k = idx >> 4, cq = idx & 15;
            *(float4*)&Ws[k][cq * 4] = W4[(size_t)(kbase + c * 32 + k) * 16 + cq];
        }
        __syncthreads();
#pragma unroll
        for (int k = 0; k < 32; k++) {
            ulonglong2 w0 = *(const ulonglong2*)&Ws[k][colg * 8];
            ulonglong2 w1 = *(const ulonglong2*)&Ws[k][colg * 8 + 4];
            ull hp0 = pack2(hs[rp * 2 + 0][k]);
            ull hp1 = pack2(hs[rp * 2 + 1][k]);
            fma2(acc[0][0], hp0, w0.x); fma2(acc[0][1], hp0, w0.y);
            fma2(acc[0][2], hp0, w1.x); fma2(acc[0][3], hp0, w1.y);
            fma2(acc[1][0], hp1, w0.x); fma2(acc[1][1], hp1, w0.y);
            fma2(acc[1][2], hp1, w1.x); fma2(acc[1][3], hp1, w1.y);
        }
    }

    float* wp = g_whp + (size_t)blockIdx.y * Bd * Nd * F_OUT;
#pragma unroll
    for (int m = 0; m < 2; m++) {
        int row = row0 + rp * 2 + m;
        float w[8];
        unpack2(w[0], w[1], acc[m][0]); unpack2(w[2], w[3], acc[m][1]);
        unpack2(w[4], w[5], acc[m][2]); unpack2(w[6], w[7], acc[m][3]);
        *(float4*)(wp + (size_t)row * F_OUT + colg * 8)     = make_float4(w[0], w[1], w[2], w[3]);
        *(float4*)(wp + (size_t)row * F_OUT + colg * 8 + 4) = make_float4(w[4], w[5], w[6], w[7]);
    }
}

// ---------------------------------------------------------------------------
// Kernel 1b: combine wh partials -> Wh, and compute es/ed in the same pass.
// Pure bandwidth (16 MB read, 4 MB write).
// ---------------------------------------------------------------------------
__global__ __launch_bounds__(256) void wh_combine(const float* __restrict__ a) {
    int tid = blockIdx.x * 256 + threadIdx.x;   // 0 .. B*N*16-1
    int row = tid >> 4;
    int c4  = tid & 15;

    float4 s = make_float4(0.f, 0.f, 0.f, 0.f);
#pragma unroll
    for (int sp = 0; sp < KSPLIT; sp++) {
        float4 v = *(const float4*)(g_whp + ((size_t)sp * Bd * Nd + row) * F_OUT + c4 * 4);
        s.x += v.x; s.y += v.y; s.z += v.z; s.w += v.w;
    }
    *(float4*)(g_Wh + (size_t)row * F_OUT + c4 * 4) = s;

    float4 a1 = ((const float4*)a)[c4];
    float4 a2 = ((const float4*)a)[16 + c4];
    float p = s.x * a1.x + s.y * a1.y + s.z * a1.z + s.w * a1.w;
    float q = s.x * a2.x + s.y * a2.y + s.z * a2.z + s.w * a2.w;
#pragma unroll
    for (int off = 8; off > 0; off >>= 1) {
        p += __shfl_xor_sync(0xFFFFFFFFu, p, off);
        q += __shfl_xor_sync(0xFFFFFFFFu, q, off);
    }
    if (c4 == 0) {
        g_es[row] = p;
        g_ed[row] = q;
    }
}

// ---------------------------------------------------------------------------
// Kernel 2: fused attention + aggregation, split-K over j (4-way). P tile
// stored TRANSPOSED+swizzled in smem so both GEMM operands are LDS.128; 4x4
// micro-tile via FFMA2. adj AND ed for the next tile are prefetched into
// registers, which also removes the ed smem staging and one of the three
// per-tile barriers. No max-subtraction needed (scores bounded ~10).
// ---------------------------------------------------------------------------
__global__ __launch_bounds__(256, 4) void gat_kernel(const int* __restrict__ adj) {
    __shared__ float PsT[TJ][PST];
    __shared__ float Whs[TJ][PST];
    __shared__ float es_s[TI];
    __shared__ float rowsum[TI];

    int t     = threadIdx.x;
    int b     = blockIdx.y;
    int i0    = blockIdx.x * TI;
    int split = blockIdx.z;
    int jbase = split * JPB;
    int jend  = jbase + JPB;

    if (t < TI) rowsum[t] = 0.f;
    if (t < 16) ((float4*)es_s)[t] = ((const float4*)(g_es + (size_t)b * Nd + i0))[t];

    int pi = t >> 2;
    int jq = t & 3;

    int ty = t >> 4;
    int tx = t & 15;
    ull acc[4][2] = {};

    const float*  Whb  = g_Wh + (size_t)b * Nd * F_OUT;
    const float4* ed4  = (const float4*)(g_ed + (size_t)b * Nd);
    const int4*   arow = (const int4*)(adj + (size_t)b * Nd * Nd + (size_t)(i0 + pi) * Nd);

    int lr = t >> 2;
    int lp = t & 3;

    // prefetch adj + ed for the first tile
    int4   av[4];
    float4 ev[4];
#pragma unroll
    for (int q = 0; q < 4; q++) {
        av[q] = arow[(jbase >> 2) + jq * 4 + q];
        ev[q] = ed4[(jbase >> 2) + jq * 4 + q];
    }
    __syncthreads();   // es_s / rowsum ready
    float esi = es_s[pi];

    for (int j0 = jbase; j0 < jend; j0 += TJ) {
        // barrier A: previous GEMM done reading PsT/Whs
        __syncthreads();

        {   // stage Wh tile
            const float4* src = (const float4*)(Whb + (size_t)(j0 + lr) * F_OUT);
            float4* dst = (float4*)&Whs[lr][0];
#pragma unroll
            for (int q = 0; q < 4; q++) dst[lp * 4 + q] = src[lp * 4 + q];
        }

        // P tile (transposed+swizzled) + partial row sums, all from registers
        float psum = 0.f;
#pragma unroll
        for (int q = 0; q < 4; q++) {
            int4   a4 = av[q];
            float4 e4 = ev[q];
            int jb  = jq * 16 + q * 4;
            int col = pi ^ jb;
            float e, p0, p1, p2, p3;
            e = esi + e4.x; e = (e > 0.f) ? e : ALPHA * e; p0 = a4.x ? __expf(e) : 0.f;
            e = esi + e4.y; e = (e > 0.f) ? e : ALPHA * e; p1 = a4.y ? __expf(e) : 0.f;
            e = esi + e4.z; e = (e > 0.f) ? e : ALPHA * e; p2 = a4.z ? __expf(e) : 0.f;
            e = esi + e4.w; e = (e > 0.f) ? e : ALPHA * e; p3 = a4.w ? __expf(e) : 0.f;
            psum += p0 + p1 + p2 + p3;
            PsT[jb + 0][col] = p0;
            PsT[jb + 1][col] = p1;
            PsT[jb + 2][col] = p2;
            PsT[jb + 3][col] = p3;
        }
        // prefetch adj + ed for next tile (wrap on last iter; harmless)
        {
            int jn = (j0 + TJ < jend) ? j0 + TJ : jbase;
#pragma unroll
            for (int q = 0; q < 4; q++) {
                av[q] = arow[(jn >> 2) + jq * 4 + q];
                ev[q] = ed4[(jn >> 2) + jq * 4 + q];
            }
        }
        psum += __shfl_xor_sync(0xFFFFFFFFu, psum, 1);
        psum += __shfl_xor_sync(0xFFFFFFFFu, psum, 2);
        if (jq == 0) rowsum[pi] += psum;

        // barrier B: PsT/Whs staged
        __syncthreads();

        // acc += P @ Whs  (64x64x64), all-LDS.128 + FFMA2
#pragma unroll 16
        for (int k = 0; k < TJ; k++) {
            float4 pv = *(const float4*)&PsT[k][(ty * 4) ^ (k & 0x3C)];
            ulonglong2 bv = *(const ulonglong2*)&Whs[k][tx * 4];
            ull a0 = pack2(pv.x), a1 = pack2(pv.y), a2 = pack2(pv.z), a3 = pack2(pv.w);
            fma2(acc[0][0], a0, bv.x); fma2(acc[0][1], a0, bv.y);
            fma2(acc[1][0], a1, bv.x); fma2(acc[1][1], a1, bv.y);
            fma2(acc[2][0], a2, bv.x); fma2(acc[2][1], a2, bv.y);
            fma2(acc[3][0], a3, bv.x); fma2(acc[3][1], a3, bv.y);
        }
    }
    __syncthreads();

    // write unnormalized partials + partial rowsums
    float* pacc = g_pacc + (((size_t)split * Bd + b) * Nd + i0) * F_OUT;
#pragma unroll
    for (int m = 0; m < 4; m++) {
        float4 o;
        unpack2(o.x, o.y, acc[m][0]);
        unpack2(o.z, o.w, acc[m][1]);
        *(float4*)(pacc + (size_t)(ty * 4 + m) * F_OUT + tx * 4) = o;
    }
    if (t < TI) g_prs[((size_t)split * Bd + b) * Nd + i0 + t] = rowsum[t];
}

// ---------------------------------------------------------------------------
// Kernel 3: sum the split partials, normalize, ELU, store.
// ---------------------------------------------------------------------------
__global__ __launch_bounds__(256) void reduce_kernel(float* __restrict__ out) {
    int tid = blockIdx.x * 256 + threadIdx.x;   // 0 .. B*N*16-1
    int row = tid >> 4;                          // b*N + i
    int c4  = tid & 15;

    float4 s = make_float4(0.f, 0.f, 0.f, 0.f);
    float rs = 0.f;
#pragma unroll
    for (int sp = 0; sp < SPLIT; sp++) {
        float4 v = *(const float4*)(g_pacc + ((size_t)sp * Bd * Nd + row) * F_OUT + c4 * 4);
        s.x += v.x; s.y += v.y; s.z += v.z; s.w += v.w;
        rs += g_prs[(size_t)sp * Bd * Nd + row];
    }
    float inv = 1.0f / rs;
    float4 o; float v;
    v = s.x * inv; o.x = (v > 0.f) ? v : expm1f(v);
    v = s.y * inv; o.y = (v > 0.f) ? v : expm1f(v);
    v = s.z * inv; o.z = (v > 0.f) ? v : expm1f(v);
    v = s.w * inv; o.w = (v > 0.f) ? v : expm1f(v);
    *(float4*)(out + (size_t)row * F_OUT + c4 * 4) = o;
}

// ---------------------------------------------------------------------------
extern "C" void kernel_launch(void* const* d_in, const int* in_sizes, int n_in,
                              void* d_out, int out_size) {
    const float* h   = (const float*)d_in[0];   // (8,2048,256) f32
    const int*   adj = (const int*)d_in[1];     // (8,2048,2048) i32
    const float* W   = (const float*)d_in[2];   // (256,64) f32
    const float* a   = (const float*)d_in[3];   // (128,1) f32
    float* out = (float*)d_out;                 // (8,2048,64) f32

    dim3 wgrid(Bd * Nd / 32, KSPLIT);
    wh_kernel<<<wgrid, 128>>>(h, W);
    wh_combine<<<Bd * Nd * 16 / 256, 256>>>(a);
    dim3 grid(Nd / TI, Bd, SPLIT);
    gat_kernel<<<grid, 256>>>(adj);
    reduce_kernel<<<Bd * Nd * 16 / 256, 256>>>(out);
}

// round 14
// speedup vs baseline: 1.7323x; 1.4900x over previous
#include <cuda_runtime.h>
#include <cuda_bf16.h>

#define Bd 8
#define Nd 2048
#define F_IN 256
#define F_OUT 64
#define ALPHA 0.2f

#define TI 64
#define TJ 64
#define SPLIT 4
#define JPB (Nd / SPLIT)   // 512 j's per block
#define KSPLIT 4           // wh GEMM K-split (K=256 -> 64 per block)
#define BST 72             // bf16 smem row stride (elems); 144B row: ldmatrix conflict-free

typedef unsigned long long ull;
typedef unsigned int uint;

// ---- packed f32x2 helpers (sm_103a FFMA2) ----
__device__ __forceinline__ void fma2(ull& d, ull a, ull b) {
    asm("fma.rn.f32x2 %0, %1, %2, %0;" : "+l"(d) : "l"(a), "l"(b));
}
__device__ __forceinline__ ull pack2(float x) {
    ull r; asm("mov.b64 %0, {%1, %1};" : "=l"(r) : "f"(x)); return r;
}
__device__ __forceinline__ void unpack2(float& lo, float& hi, ull v) {
    asm("mov.b64 {%0, %1}, %2;" : "=f"(lo), "=f"(hi) : "l"(v));
}

// ---- bf16 / mma helpers ----
__device__ __forceinline__ uint packbf(float lo, float hi) {   // mem order: lo at lower addr
    uint d; asm("cvt.rn.bf16x2.f32 %0, %1, %2;" : "=r"(d) : "f"(hi), "f"(lo)); return d;
}
__device__ __forceinline__ float bfround(float x) {
    return __bfloat162float(__float2bfloat16(x));
}
__device__ __forceinline__ uint su32(const void* p) {
    return (uint)__cvta_generic_to_shared(p);
}
__device__ __forceinline__ void ldsmA(uint r[4], uint addr) {
    asm volatile("ldmatrix.sync.aligned.m8n8.x4.shared.b16 {%0,%1,%2,%3}, [%4];"
                 : "=r"(r[0]), "=r"(r[1]), "=r"(r[2]), "=r"(r[3]) : "r"(addr));
}
__device__ __forceinline__ void ldsmBT(uint r[4], uint addr) {
    asm volatile("ldmatrix.sync.aligned.m8n8.x4.trans.shared.b16 {%0,%1,%2,%3}, [%4];"
                 : "=r"(r[0]), "=r"(r[1]), "=r"(r[2]), "=r"(r[3]) : "r"(addr));
}
__device__ __forceinline__ void mma_bf16(float c[4], const uint a[4], uint b0, uint b1) {
    asm volatile("mma.sync.aligned.m16n8k16.row.col.f32.bf16.bf16.f32 "
                 "{%0,%1,%2,%3}, {%4,%5,%6,%7}, {%8,%9}, {%0,%1,%2,%3};"
                 : "+f"(c[0]), "+f"(c[1]), "+f"(c[2]), "+f"(c[3])
                 : "r"(a[0]), "r"(a[1]), "r"(a[2]), "r"(a[3]), "r"(b0), "r"(b1));
}

// ---- scratch (__device__ globals; allocation-free rule) ----
__device__ __align__(16) float g_Wh[Bd * Nd * F_OUT];             // unused downstream but cheap
__device__ __align__(16) float g_whp[KSPLIT * Bd * Nd * F_OUT];   // 16 MB wh partials
__device__ __align__(16) __nv_bfloat16 g_Whhi[Bd * Nd * F_OUT];   // 2 MB
__device__ __align__(16) __nv_bfloat16 g_Wlo [Bd * Nd * F_OUT];   // 2 MB
__device__ __align__(16) float g_es[Bd * Nd];
__device__ __align__(16) float g_ed[Bd * Nd];
__device__ __align__(16) float g_pacc[SPLIT * Bd * Nd * F_OUT];   // 16 MB gat partials
__device__ __align__(16) float g_prs[SPLIT * Bd * Nd];            // partial rowsums

// ---------------------------------------------------------------------------
// Kernel 1a: Wh partials, split-K 4-way (unchanged from best config).
// ---------------------------------------------------------------------------
__global__ __launch_bounds__(128) void wh_kernel(const float* __restrict__ h,
                                                 const float* __restrict__ W) {
    __shared__ float hs[32][36];
    __shared__ float Ws[32][72];

    int t     = threadIdx.x;
    int row0  = blockIdx.x * 32;
    int kbase = blockIdx.y * 64;
    int colg  = t & 7;
    int rp    = t >> 3;

    const float4* h4 = (const float4*)h;
    const float4* W4 = (const float4*)W;

    ull acc[2][4] = {};

    for (int c = 0; c < 2; c++) {
        __syncthreads();
#pragma unroll
        for (int q = 0; q < 2; q++) {
            int idx = t * 2 + q;
            int r = idx >> 3, kq = idx & 7;
            *(float4*)&hs[r][kq * 4] =
                h4[(size_t)(row0 + r) * 64 + (kbase >> 2) + c * 8 + kq];
        }
#pragma unroll
        for (int q = 0; q < 4; q++) {
            int idx = t * 4 + q;
            int k = idx >> 4, cq = idx & 15;
            *(float4*)&Ws[k][cq * 4] = W4[(size_t)(kbase + c * 32 + k) * 16 + cq];
        }
        __syncthreads();
#pragma unroll
        for (int k = 0; k < 32; k++) {
            ulonglong2 w0 = *(const ulonglong2*)&Ws[k][colg * 8];
            ulonglong2 w1 = *(const ulonglong2*)&Ws[k][colg * 8 + 4];
            ull hp0 = pack2(hs[rp * 2 + 0][k]);
            ull hp1 = pack2(hs[rp * 2 + 1][k]);
            fma2(acc[0][0], hp0, w0.x); fma2(acc[0][1], hp0, w0.y);
            fma2(acc[0][2], hp0, w1.x); fma2(acc[0][3], hp0, w1.y);
            fma2(acc[1][0], hp1, w0.x); fma2(acc[1][1], hp1, w0.y);
            fma2(acc[1][2], hp1, w1.x); fma2(acc[1][3], hp1, w1.y);
        }
    }

    float* wp = g_whp + (size_t)blockIdx.y * Bd * Nd * F_OUT;
#pragma unroll
    for (int m = 0; m < 2; m++) {
        int row = row0 + rp * 2 + m;
        float w[8];
        unpack2(w[0], w[1], acc[m][0]); unpack2(w[2], w[3], acc[m][1]);
        unpack2(w[4], w[5], acc[m][2]); unpack2(w[6], w[7], acc[m][3]);
        *(float4*)(wp + (size_t)row * F_OUT + colg * 8)     = make_float4(w[0], w[1], w[2], w[3]);
        *(float4*)(wp + (size_t)row * F_OUT + colg * 8 + 4) = make_float4(w[4], w[5], w[6], w[7]);
    }
}

// ---------------------------------------------------------------------------
// Kernel 1b: combine wh partials -> bf16 hi/lo split of Wh, plus es/ed.
// ---------------------------------------------------------------------------
__global__ __launch_bounds__(256) void wh_combine(const float* __restrict__ a) {
    int tid = blockIdx.x * 256 + threadIdx.x;   // 0 .. B*N*16-1
    int row = tid >> 4;
    int c4  = tid & 15;

    float4 s = make_float4(0.f, 0.f, 0.f, 0.f);
#pragma unroll
    for (int sp = 0; sp < KSPLIT; sp++) {
        float4 v = *(const float4*)(g_whp + ((size_t)sp * Bd * Nd + row) * F_OUT + c4 * 4);
        s.x += v.x; s.y += v.y; s.z += v.z; s.w += v.w;
    }
    // hi/lo bf16 split (error-compensated tensor path)
    float hx = bfround(s.x), hy = bfround(s.y), hz = bfround(s.z), hw = bfround(s.w);
    uint2 uh, ul;
    uh.x = packbf(hx, hy);                    uh.y = packbf(hz, hw);
    ul.x = packbf(s.x - hx, s.y - hy);        ul.y = packbf(s.z - hz, s.w - hw);
    *(uint2*)&g_Whhi[(size_t)row * F_OUT + c4 * 4] = uh;
    *(uint2*)&g_Wlo [(size_t)row * F_OUT + c4 * 4] = ul;

    float4 a1 = ((const float4*)a)[c4];
    float4 a2 = ((const float4*)a)[16 + c4];
    float p = s.x * a1.x + s.y * a1.y + s.z * a1.z + s.w * a1.w;
    float q = s.x * a2.x + s.y * a2.y + s.z * a2.z + s.w * a2.w;
#pragma unroll
    for (int off = 8; off > 0; off >>= 1) {
        p += __shfl_xor_sync(0xFFFFFFFFu, p, off);
        q += __shfl_xor_sync(0xFFFFFFFFu, q, off);
    }
    if (c4 == 0) {
        g_es[row] = p;
        g_ed[row] = q;
    }
}

// ---------------------------------------------------------------------------
// Kernel 2: fused attention + aggregation on the TENSOR pipe.
// P (fp32, exact for rowsum) is split into bf16 hi/lo tiles in smem; Wh hi/lo
// staged from precomputed bf16 globals. GEMM = 3 compensated HMMA passes:
// Phi@Whi + Phi@Wlo + Plo@Whi (residual ~2^-16). 8 warps: warp = (m-block,
// n-half); ldmatrix A row-major / B trans, 144B stride -> conflict-free.
// ---------------------------------------------------------------------------
__global__ __launch_bounds__(256, 3) void gat_kernel(const int* __restrict__ adj) {
    __shared__ __align__(16) __nv_bfloat16 Ahi[TI * BST];
    __shared__ __align__(16) __nv_bfloat16 Alo[TI * BST];
    __shared__ __align__(16) __nv_bfloat16 Bhi[TJ * BST];
    __shared__ __align__(16) __nv_bfloat16 Blo[TJ * BST];
    __shared__ float es_s[TI];
    __shared__ float rowsum[TI];

    int t     = threadIdx.x;
    int b     = blockIdx.y;
    int i0    = blockIdx.x * TI;
    int split = blockIdx.z;
    int jbase = split * JPB;
    int jend  = jbase + JPB;

    if (t < TI) rowsum[t] = 0.f;
    if (t < 16) ((float4*)es_s)[t] = ((const float4*)(g_es + (size_t)b * Nd + i0))[t];

    int pi = t >> 2;           // P-gen row 0..63
    int jq = t & 3;            // j-quad

    // mma mapping
    int w    = t >> 5;         // warp 0..7
    int mb   = w >> 1;         // m-block 0..3 (rows mb*16..+15)
    int nh   = w & 1;          // n-half (cols nh*32..+31)
    int lane = t & 31;
    int matv = lane >> 3;
    int arow = mb * 16 + (lane & 7) + (matv & 1) * 8;
    int acol = (matv >> 1) * 8;
    int krow = (lane & 7) + (matv & 1) * 8;
    int ncol = nh * 32 + (matv >> 1) * 8;
    uint aAhi = su32(Ahi) + arow * 144 + acol * 2;
    uint aAlo = su32(Alo) + arow * 144 + acol * 2;
    uint aBhi = su32(Bhi) + krow * 144 + ncol * 2;
    uint aBlo = su32(Blo) + krow * 144 + ncol * 2;

    float cacc[4][4] = {};     // 4 n-blocks x m16n8 fragment

    const __nv_bfloat16* Whhib = g_Whhi + (size_t)b * Nd * F_OUT;
    const __nv_bfloat16* Wlob  = g_Wlo  + (size_t)b * Nd * F_OUT;
    const float4* ed4  = (const float4*)(g_ed + (size_t)b * Nd);
    const int4*   arj  = (const int4*)(adj + (size_t)b * Nd * Nd + (size_t)(i0 + pi) * Nd);

    int lr = t >> 2;           // B staging: row in tile
    int lp = t & 3;            // 16-bf16 group

    // prefetch adj + ed for the first tile
    int4   av[4];
    float4 ev[4];
#pragma unroll
    for (int q = 0; q < 4; q++) {
        av[q] = arj[(jbase >> 2) + jq * 4 + q];
        ev[q] = ed4[(jbase >> 2) + jq * 4 + q];
    }
    __syncthreads();           // es_s / rowsum ready
    float esi = es_s[pi];

    for (int j0 = jbase; j0 < jend; j0 += TJ) {
        __syncthreads();       // barrier A: previous MMA done reading tiles

        {   // stage Wh hi/lo bf16 tiles (row lr, cols lp*16..+15)
            const uint4* shi = (const uint4*)(Whhib + (size_t)(j0 + lr) * F_OUT + lp * 16);
            const uint4* slo = (const uint4*)(Wlob  + (size_t)(j0 + lr) * F_OUT + lp * 16);
            *(uint4*)&Bhi[lr * BST + lp * 16 + 0] = shi[0];
            *(uint4*)&Bhi[lr * BST + lp * 16 + 8] = shi[1];
            *(uint4*)&Blo[lr * BST + lp * 16 + 0] = slo[0];
            *(uint4*)&Blo[lr * BST + lp * 16 + 8] = slo[1];
        }

        // P tile: fp32 -> psum (exact), then bf16 hi/lo split into smem
        float psum = 0.f;
#pragma unroll
        for (int q = 0; q < 4; q++) {
            int4   a4 = av[q];
            float4 e4 = ev[q];
            int jb = jq * 16 + q * 4;
            float e, p0, p1, p2, p3;
            e = esi + e4.x; e = (e > 0.f) ? e : ALPHA * e; p0 = a4.x ? __expf(e) : 0.f;
            e = esi + e4.y; e = (e > 0.f) ? e : ALPHA * e; p1 = a4.y ? __expf(e) : 0.f;
            e = esi + e4.z; e = (e > 0.f) ? e : ALPHA * e; p2 = a4.z ? __expf(e) : 0.f;
            e = esi + e4.w; e = (e > 0.f) ? e : ALPHA * e; p3 = a4.w ? __expf(e) : 0.f;
            psum += p0 + p1 + p2 + p3;
            float h0 = bfround(p0), h1 = bfround(p1), h2 = bfround(p2), h3 = bfround(p3);
            uint uh0 = packbf(h0, h1), uh1 = packbf(h2, h3);
            uint ul0 = packbf(p0 - h0, p1 - h1), ul1 = packbf(p2 - h2, p3 - h3);
            *(ull*)&Ahi[pi * BST + jb] = (ull)uh0 | ((ull)uh1 << 32);
            *(ull*)&Alo[pi * BST + jb] = (ull)ul0 | ((ull)ul1 << 32);
        }
        // prefetch adj + ed for next tile (wrap on last iter; harmless)
        {
            int jn = (j0 + TJ < jend) ? j0 + TJ : jbase;
#pragma unroll
            for (int q = 0; q < 4; q++) {
                av[q] = arj[(jn >> 2) + jq * 4 + q];
                ev[q] = ed4[(jn >> 2) + jq * 4 + q];
            }
        }
        psum += __shfl_xor_sync(0xFFFFFFFFu, psum, 1);
        psum += __shfl_xor_sync(0xFFFFFFFFu, psum, 2);
        if (jq == 0) rowsum[pi] += psum;

        __syncthreads();       // barrier B: tiles staged

        // 3-term compensated HMMA: Phi@Whi + Phi@Wlo + Plo@Whi
#pragma unroll
        for (int kk = 0; kk < 4; kk++) {
            uint ah[4], al[4];
            ldsmA(ah, aAhi + kk * 32);
            ldsmA(al, aAlo + kk * 32);
#pragma unroll
            for (int nb2 = 0; nb2 < 2; nb2++) {
                uint bh[4], bl[4];
                ldsmBT(bh, aBhi + kk * 2304 + nb2 * 32);   // kk*16 rows * 144B; nb2*16 cols * 2B
                ldsmBT(bl, aBlo + kk * 2304 + nb2 * 32);
                mma_bf16(cacc[nb2 * 2 + 0], ah, bh[0], bh[1]);
                mma_bf16(cacc[nb2 * 2 + 1], ah, bh[2], bh[3]);
                mma_bf16(cacc[nb2 * 2 + 0], ah, bl[0], bl[1]);
                mma_bf16(cacc[nb2 * 2 + 1], ah, bl[2], bl[3]);
                mma_bf16(cacc[nb2 * 2 + 0], al, bh[0], bh[1]);
                mma_bf16(cacc[nb2 * 2 + 1], al, bh[2], bh[3]);
            }
        }
    }
    __syncthreads();

    // epilogue: write unnormalized partials (C fragment layout) + rowsums
    float* pacc = g_pacc + (((size_t)split * Bd + b) * Nd + i0) * F_OUT;
    int g  = lane >> 2;
    int cp = (lane & 3) * 2;
#pragma unroll
    for (int nb = 0; nb < 4; nb++) {
        int col  = nh * 32 + nb * 8 + cp;
        int row0 = mb * 16 + g;
        *(float2*)(pacc + (size_t)row0 * F_OUT + col)       = make_float2(cacc[nb][0], cacc[nb][1]);
        *(float2*)(pacc + (size_t)(row0 + 8) * F_OUT + col) = make_float2(cacc[nb][2], cacc[nb][3]);
    }
    if (t < TI) g_prs[((size_t)split * Bd + b) * Nd + i0 + t] = rowsum[t];
}

// ---------------------------------------------------------------------------
// Kernel 3: sum the split partials, normalize, ELU, store.
// ---------------------------------------------------------------------------
__global__ __launch_bounds__(256) void reduce_kernel(float* __restrict__ out) {
    int tid = blockIdx.x * 256 + threadIdx.x;   // 0 .. B*N*16-1
    int row = tid >> 4;
    int c4  = tid & 15;

    float4 s = make_float4(0.f, 0.f, 0.f, 0.f);
    float rs = 0.f;
#pragma unroll
    for (int sp = 0; sp < SPLIT; sp++) {
        float4 v = *(const float4*)(g_pacc + ((size_t)sp * Bd * Nd + row) * F_OUT + c4 * 4);
        s.x += v.x; s.y += v.y; s.z += v.z; s.w += v.w;
        rs += g_prs[(size_t)sp * Bd * Nd + row];
    }
    float inv = 1.0f / rs;
    float4 o; float v;
    v = s.x * inv; o.x = (v > 0.f) ? v : expm1f(v);
    v = s.y * inv; o.y = (v > 0.f) ? v : expm1f(v);
    v = s.z * inv; o.z = (v > 0.f) ? v : expm1f(v);
    v = s.w * inv; o.w = (v > 0.f) ? v : expm1f(v);
    *(float4*)(out + (size_t)row * F_OUT + c4 * 4) = o;
}

// ---------------------------------------------------------------------------
extern "C" void kernel_launch(void* const* d_in, const int* in_sizes, int n_in,
                              void* d_out, int out_size) {
    const float* h   = (const float*)d_in[0];   // (8,2048,256) f32
    const int*   adj = (const int*)d_in[1];     // (8,2048,2048) i32
    const float* W   = (const float*)d_in[2];   // (256,64) f32
    const float* a   = (const float*)d_in[3];   // (128,1) f32
    float* out = (float*)d_out;                 // (8,2048,64) f32

    dim3 wgrid(Bd * Nd / 32, KSPLIT);
    wh_kernel<<<wgrid, 128>>>(h, W);
    wh_combine<<<Bd * Nd * 16 / 256, 256>>>(a);
    dim3 grid(Nd / TI, Bd, SPLIT);
    gat_kernel<<<grid, 256>>>(adj);
    reduce_kernel<<<Bd * Nd * 16 / 256, 256>>>(out);
}

// round 15
// speedup vs baseline: 1.7976x; 1.0377x over previous
#include <cuda_runtime.h>
#include <cuda_bf16.h>

#define Bd 8
#define Nd 2048
#define F_IN 256
#define F_OUT 64
#define ALPHA 0.2f

#define TI 64
#define TJ 64
#define SPLIT 4
#define JPB (Nd / SPLIT)   // 512 j's per block
#define KSPLIT 4           // wh GEMM K-split (K=256 -> 64 per block)
#define BST 72             // bf16 smem row stride (elems); 144B row: ldmatrix conflict-free
#define NTILES (Nd / TI)   // 32 i-tiles

typedef unsigned long long ull;
typedef unsigned int uint;

// ---- packed f32x2 helpers (sm_103a FFMA2) ----
__device__ __forceinline__ void fma2(ull& d, ull a, ull b) {
    asm("fma.rn.f32x2 %0, %1, %2, %0;" : "+l"(d) : "l"(a), "l"(b));
}
__device__ __forceinline__ ull pack2(float x) {
    ull r; asm("mov.b64 %0, {%1, %1};" : "=l"(r) : "f"(x)); return r;
}
__device__ __forceinline__ void unpack2(float& lo, float& hi, ull v) {
    asm("mov.b64 {%0, %1}, %2;" : "=f"(lo), "=f"(hi) : "l"(v));
}

// ---- bf16 / mma helpers ----
__device__ __forceinline__ uint packbf(float lo, float hi) {   // mem order: lo at lower addr
    uint d; asm("cvt.rn.bf16x2.f32 %0, %1, %2;" : "=r"(d) : "f"(hi), "f"(lo)); return d;
}
__device__ __forceinline__ float bfround(float x) {
    return __bfloat162float(__float2bfloat16(x));
}
__device__ __forceinline__ uint su32(const void* p) {
    return (uint)__cvta_generic_to_shared(p);
}
__device__ __forceinline__ void ldsmA(uint r[4], uint addr) {
    asm volatile("ldmatrix.sync.aligned.m8n8.x4.shared.b16 {%0,%1,%2,%3}, [%4];"
                 : "=r"(r[0]), "=r"(r[1]), "=r"(r[2]), "=r"(r[3]) : "r"(addr));
}
__device__ __forceinline__ void ldsmBT(uint r[4], uint addr) {
    asm volatile("ldmatrix.sync.aligned.m8n8.x4.trans.shared.b16 {%0,%1,%2,%3}, [%4];"
                 : "=r"(r[0]), "=r"(r[1]), "=r"(r[2]), "=r"(r[3]) : "r"(addr));
}
__device__ __forceinline__ void mma_bf16(float c[4], const uint a[4], uint b0, uint b1) {
    asm volatile("mma.sync.aligned.m16n8k16.row.col.f32.bf16.bf16.f32 "
                 "{%0,%1,%2,%3}, {%4,%5,%6,%7}, {%8,%9}, {%0,%1,%2,%3};"
                 : "+f"(c[0]), "+f"(c[1]), "+f"(c[2]), "+f"(c[3])
                 : "r"(a[0]), "r"(a[1]), "r"(a[2]), "r"(a[3]), "r"(b0), "r"(b1));
}
__device__ __forceinline__ void cpasync16(uint s, const void* g) {
    asm volatile("cp.async.cg.shared.global [%0], [%1], 16;" :: "r"(s), "l"(g));
}
__device__ __forceinline__ void cp_commit() { asm volatile("cp.async.commit_group;"); }
__device__ __forceinline__ void cp_wait0()  { asm volatile("cp.async.wait_group 0;" ::: "memory"); }

// ---- scratch (__device__ globals; allocation-free rule) ----
__device__ __align__(16) float g_whp[KSPLIT * Bd * Nd * F_OUT];   // 16 MB wh partials
__device__ __align__(16) __nv_bfloat16 g_Whhi[Bd * Nd * F_OUT];   // 2 MB
__device__ __align__(16) __nv_bfloat16 g_Wlo [Bd * Nd * F_OUT];   // 2 MB
__device__ __align__(16) float g_es[Bd * Nd];
__device__ __align__(16) float g_ed[Bd * Nd];
__device__ __align__(16) float g_pacc[SPLIT * Bd * Nd * F_OUT];   // 16 MB gat partials
__device__ __align__(16) float g_prs[SPLIT * Bd * Nd];            // partial rowsums
__device__ int g_ctr[Bd * NTILES];                                // tile arrival counters (zero-init)

// ---------------------------------------------------------------------------
// Kernel 1a: Wh partials, split-K 4-way (unchanged best config).
// ---------------------------------------------------------------------------
__global__ __launch_bounds__(128) void wh_kernel(const float* __restrict__ h,
                                                 const float* __restrict__ W) {
    __shared__ float hs[32][36];
    __shared__ float Ws[32][72];

    int t     = threadIdx.x;
    int row0  = blockIdx.x * 32;
    int kbase = blockIdx.y * 64;
    int colg  = t & 7;
    int rp    = t >> 3;

    const float4* h4 = (const float4*)h;
    const float4* W4 = (const float4*)W;

    ull acc[2][4] = {};

    for (int c = 0; c < 2; c++) {
        __syncthreads();
#pragma unroll
        for (int q = 0; q < 2; q++) {
            int idx = t * 2 + q;
            int r = idx >> 3, kq = idx & 7;
            *(float4*)&hs[r][kq * 4] =
                h4[(size_t)(row0 + r) * 64 + (kbase >> 2) + c * 8 + kq];
        }
#pragma unroll
        for (int q = 0; q < 4; q++) {
            int idx = t * 4 + q;
            int k = idx >> 4, cq = idx & 15;
            *(float4*)&Ws[k][cq * 4] = W4[(size_t)(kbase + c * 32 + k) * 16 + cq];
        }
        __syncthreads();
#pragma unroll
        for (int k = 0; k < 32; k++) {
            ulonglong2 w0 = *(const ulonglong2*)&Ws[k][colg * 8];
            ulonglong2 w1 = *(const ulonglong2*)&Ws[k][colg * 8 + 4];
            ull hp0 = pack2(hs[rp * 2 + 0][k]);
            ull hp1 = pack2(hs[rp * 2 + 1][k]);
            fma2(acc[0][0], hp0, w0.x); fma2(acc[0][1], hp0, w0.y);
            fma2(acc[0][2], hp0, w1.x); fma2(acc[0][3], hp0, w1.y);
            fma2(acc[1][0], hp1, w0.x); fma2(acc[1][1], hp1, w0.y);
            fma2(acc[1][2], hp1, w1.x); fma2(acc[1][3], hp1, w1.y);
        }
    }

    float* wp = g_whp + (size_t)blockIdx.y * Bd * Nd * F_OUT;
#pragma unroll
    for (int m = 0; m < 2; m++) {
        int row = row0 + rp * 2 + m;
        float w[8];
        unpack2(w[0], w[1], acc[m][0]); unpack2(w[2], w[3], acc[m][1]);
        unpack2(w[4], w[5], acc[m][2]); unpack2(w[6], w[7], acc[m][3]);
        *(float4*)(wp + (size_t)row * F_OUT + colg * 8)     = make_float4(w[0], w[1], w[2], w[3]);
        *(float4*)(wp + (size_t)row * F_OUT + colg * 8 + 4) = make_float4(w[4], w[5], w[6], w[7]);
    }
}

// ---------------------------------------------------------------------------
// Kernel 1b: combine wh partials -> bf16 hi/lo split of Wh, plus es/ed.
// (W side uses round-based split: precomputed, so use the tighter bound.)
// ---------------------------------------------------------------------------
__global__ __launch_bounds__(256) void wh_combine(const float* __restrict__ a) {
    int tid = blockIdx.x * 256 + threadIdx.x;   // 0 .. B*N*16-1
    int row = tid >> 4;
    int c4  = tid & 15;

    float4 s = make_float4(0.f, 0.f, 0.f, 0.f);
#pragma unroll
    for (int sp = 0; sp < KSPLIT; sp++) {
        float4 v = *(const float4*)(g_whp + ((size_t)sp * Bd * Nd + row) * F_OUT + c4 * 4);
        s.x += v.x; s.y += v.y; s.z += v.z; s.w += v.w;
    }
    float hx = bfround(s.x), hy = bfround(s.y), hz = bfround(s.z), hw = bfround(s.w);
    uint2 uh, ul;
    uh.x = packbf(hx, hy);                    uh.y = packbf(hz, hw);
    ul.x = packbf(s.x - hx, s.y - hy);        ul.y = packbf(s.z - hz, s.w - hw);
    *(uint2*)&g_Whhi[(size_t)row * F_OUT + c4 * 4] = uh;
    *(uint2*)&g_Wlo [(size_t)row * F_OUT + c4 * 4] = ul;

    float4 a1 = ((const float4*)a)[c4];
    float4 a2 = ((const float4*)a)[16 + c4];
    float p = s.x * a1.x + s.y * a1.y + s.z * a1.z + s.w * a1.w;
    float q = s.x * a2.x + s.y * a2.y + s.z * a2.z + s.w * a2.w;
#pragma unroll
    for (int off = 8; off > 0; off >>= 1) {
        p += __shfl_xor_sync(0xFFFFFFFFu, p, off);
        q += __shfl_xor_sync(0xFFFFFFFFu, q, off);
    }
    if (c4 == 0) {
        g_es[row] = p;
        g_ed[row] = q;
    }
}

// ---------------------------------------------------------------------------
// Kernel 2: fused attention + aggregation + LAST-BLOCK REDUCTION.
// - B tiles (Wh hi/lo) staged via cp.async, overlapped with P-generation.
// - P hi = bit-truncated bf16 (exact, PRMT-packed), lo = p - hi (1 cvt/pair).
// - 3-term compensated HMMA: Phi@Whi + Phi@Wlo + Plo@Whi.
// - After partial writes, last-arriving split block per (b,i0) tile sums the
//   4 partials in fixed order (deterministic), normalizes, ELUs, stores out.
//   Counter self-resets to 0 for graph replay.
// ---------------------------------------------------------------------------
__global__ __launch_bounds__(256, 3) void gat_kernel(const int* __restrict__ adj,
                                                     float* __restrict__ out) {
    __shared__ __align__(16) __nv_bfloat16 Ahi[TI * BST];
    __shared__ __align__(16) __nv_bfloat16 Alo[TI * BST];
    __shared__ __align__(16) __nv_bfloat16 Bhi[TJ * BST];
    __shared__ __align__(16) __nv_bfloat16 Blo[TJ * BST];
    __shared__ float es_s[TI];
    __shared__ float rowsum[TI];
    __shared__ int   is_last;

    int t     = threadIdx.x;
    int b     = blockIdx.y;
    int i0    = blockIdx.x * TI;
    int split = blockIdx.z;
    int jbase = split * JPB;
    int jend  = jbase + JPB;

    if (t < TI) rowsum[t] = 0.f;
    if (t < 16) ((float4*)es_s)[t] = ((const float4*)(g_es + (size_t)b * Nd + i0))[t];

    int pi = t >> 2;           // P-gen row 0..63
    int jq = t & 3;            // j-quad

    // mma mapping
    int w    = t >> 5;         // warp 0..7
    int mb   = w >> 1;         // m-block (rows mb*16..+15)
    int nh   = w & 1;          // n-half (cols nh*32..+31)
    int lane = t & 31;
    int matv = lane >> 3;
    int arow = mb * 16 + (lane & 7) + (matv & 1) * 8;
    int acol = (matv >> 1) * 8;
    int krow = (lane & 7) + (matv & 1) * 8;
    int ncol = nh * 32 + (matv >> 1) * 8;
    uint aAhi = su32(Ahi) + arow * 144 + acol * 2;
    uint aAlo = su32(Alo) + arow * 144 + acol * 2;
    uint aBhi = su32(Bhi) + krow * 144 + ncol * 2;
    uint aBlo = su32(Blo) + krow * 144 + ncol * 2;

    float cacc[4][4] = {};

    const __nv_bfloat16* Whhib = g_Whhi + (size_t)b * Nd * F_OUT;
    const __nv_bfloat16* Wlob  = g_Wlo  + (size_t)b * Nd * F_OUT;
    const float4* ed4  = (const float4*)(g_ed + (size_t)b * Nd);
    const int4*   arj  = (const int4*)(adj + (size_t)b * Nd * Nd + (size_t)(i0 + pi) * Nd);

    int lr = t >> 2;           // B staging: row in tile
    int lp = t & 3;            // 16-bf16 group
    uint sBhi = su32(Bhi) + (lr * BST + lp * 16) * 2;
    uint sBlo = su32(Blo) + (lr * BST + lp * 16) * 2;

    // prefetch adj + ed for the first tile
    int4   av[4];
    float4 ev[4];
#pragma unroll
    for (int q = 0; q < 4; q++) {
        av[q] = arj[(jbase >> 2) + jq * 4 + q];
        ev[q] = ed4[(jbase >> 2) + jq * 4 + q];
    }
    __syncthreads();           // es_s / rowsum ready
    float esi = es_s[pi];

    for (int j0 = jbase; j0 < jend; j0 += TJ) {
        __syncthreads();       // barrier A: previous MMA done reading tiles

        // launch async B-tile copies (overlap with P-gen below)
        {
            const __nv_bfloat16* ghi = Whhib + (size_t)(j0 + lr) * F_OUT + lp * 16;
            const __nv_bfloat16* glo = Wlob  + (size_t)(j0 + lr) * F_OUT + lp * 16;
            cpasync16(sBhi,      ghi);
            cpasync16(sBhi + 16, ghi + 8);
            cpasync16(sBlo,      glo);
            cpasync16(sBlo + 16, glo + 8);
            cp_commit();
        }

        // P tile: fp32 psum (exact) + truncation hi/lo split into smem
        float psum = 0.f;
#pragma unroll
        for (int q = 0; q < 4; q++) {
            int4   a4 = av[q];
            float4 e4 = ev[q];
            int jb = jq * 16 + q * 4;
            float e, p0, p1, p2, p3;
            e = esi + e4.x; e = (e > 0.f) ? e : ALPHA * e; p0 = a4.x ? __expf(e) : 0.f;
            e = esi + e4.y; e = (e > 0.f) ? e : ALPHA * e; p1 = a4.y ? __expf(e) : 0.f;
            e = esi + e4.z; e = (e > 0.f) ? e : ALPHA * e; p2 = a4.z ? __expf(e) : 0.f;
            e = esi + e4.w; e = (e > 0.f) ? e : ALPHA * e; p3 = a4.w ? __expf(e) : 0.f;
            psum += p0 + p1 + p2 + p3;
            uint pb0 = __float_as_uint(p0), pb1 = __float_as_uint(p1);
            uint pb2 = __float_as_uint(p2), pb3 = __float_as_uint(p3);
            float l0 = p0 - __uint_as_float(pb0 & 0xFFFF0000u);
            float l1 = p1 - __uint_as_float(pb1 & 0xFFFF0000u);
            float l2 = p2 - __uint_as_float(pb2 & 0xFFFF0000u);
            float l3 = p3 - __uint_as_float(pb3 & 0xFFFF0000u);
            uint uh0 = __byte_perm(pb0, pb1, 0x7632);
            uint uh1 = __byte_perm(pb2, pb3, 0x7632);
            uint ul0 = packbf(l0, l1);
            uint ul1 = packbf(l2, l3);
            *(ull*)&Ahi[pi * BST + jb] = (ull)uh0 | ((ull)uh1 << 32);
            *(ull*)&Alo[pi * BST + jb] = (ull)ul0 | ((ull)ul1 << 32);
        }
        // prefetch adj + ed for next tile (wrap on last iter; harmless)
        {
            int jn = (j0 + TJ < jend) ? j0 + TJ : jbase;
#pragma unroll
            for (int q = 0; q < 4; q++) {
                av[q] = arj[(jn >> 2) + jq * 4 + q];
                ev[q] = ed4[(jn >> 2) + jq * 4 + q];
            }
        }
        psum += __shfl_xor_sync(0xFFFFFFFFu, psum, 1);
        psum += __shfl_xor_sync(0xFFFFFFFFu, psum, 2);
        if (jq == 0) rowsum[pi] += psum;

        cp_wait0();
        __syncthreads();       // barrier B: all tiles staged

        // 3-term compensated HMMA
#pragma unroll
        for (int kk = 0; kk < 4; kk++) {
            uint ah[4], al[4];
            ldsmA(ah, aAhi + kk * 32);
            ldsmA(al, aAlo + kk * 32);
#pragma unroll
            for (int nb2 = 0; nb2 < 2; nb2++) {
                uint bh[4], bl[4];
                ldsmBT(bh, aBhi + kk * 2304 + nb2 * 32);
                ldsmBT(bl, aBlo + kk * 2304 + nb2 * 32);
                mma_bf16(cacc[nb2 * 2 + 0], ah, bh[0], bh[1]);
                mma_bf16(cacc[nb2 * 2 + 1], ah, bh[2], bh[3]);
                mma_bf16(cacc[nb2 * 2 + 0], ah, bl[0], bl[1]);
                mma_bf16(cacc[nb2 * 2 + 1], ah, bl[2], bl[3]);
                mma_bf16(cacc[nb2 * 2 + 0], al, bh[0], bh[1]);
                mma_bf16(cacc[nb2 * 2 + 1], al, bh[2], bh[3]);
            }
        }
    }
    __syncthreads();

    // write unnormalized partials (C fragment layout) + rowsums
    float* pacc = g_pacc + (((size_t)split * Bd + b) * Nd + i0) * F_OUT;
    int gg = lane >> 2;
    int cp = (lane & 3) * 2;
#pragma unroll
    for (int nb = 0; nb < 4; nb++) {
        int col  = nh * 32 + nb * 8 + cp;
        int row0 = mb * 16 + gg;
        *(float2*)(pacc + (size_t)row0 * F_OUT + col)       = make_float2(cacc[nb][0], cacc[nb][1]);
        *(float2*)(pacc + (size_t)(row0 + 8) * F_OUT + col) = make_float2(cacc[nb][2], cacc[nb][3]);
    }
    if (t < TI) g_prs[((size_t)split * Bd + b) * Nd + i0 + t] = rowsum[t];

    // last-block reduction for this (b, i0) tile
    __threadfence();
    if (t == 0) {
        int old = atomicAdd(&g_ctr[b * NTILES + blockIdx.x], 1);
        is_last = (old == SPLIT - 1) ? 1 : 0;
    }
    __syncthreads();
    if (!is_last) return;
    __threadfence();
    if (t == 0) g_ctr[b * NTILES + blockIdx.x] = 0;   // reset for next replay

#pragma unroll
    for (int g = 0; g < 4; g++) {
        int idx = g * 256 + t;         // 0..1023
        int r   = idx >> 4;            // 0..63
        int c4  = idx & 15;
        size_t rowg = (size_t)b * Nd + i0 + r;
        float4 s = make_float4(0.f, 0.f, 0.f, 0.f);
        float rs = 0.f;
#pragma unroll
        for (int sp = 0; sp < SPLIT; sp++) {
            float4 v = *(const float4*)(g_pacc + ((size_t)sp * Bd * Nd + rowg) * F_OUT + c4 * 4);
            s.x += v.x; s.y += v.y; s.z += v.z; s.w += v.w;
            rs += g_prs[(size_t)sp * Bd * Nd + rowg];
        }
        float inv = 1.0f / rs;
        float4 o; float v;
        v = s.x * inv; o.x = (v > 0.f) ? v : expm1f(v);
        v = s.y * inv; o.y = (v > 0.f) ? v : expm1f(v);
        v = s.z * inv; o.z = (v > 0.f) ? v : expm1f(v);
        v = s.w * inv; o.w = (v > 0.f) ? v : expm1f(v);
        *(float4*)(out + rowg * F_OUT + c4 * 4) = o;
    }
}

// ---------------------------------------------------------------------------
extern "C" void kernel_launch(void* const* d_in, const int* in_sizes, int n_in,
                              void* d_out, int out_size) {
    const float* h   = (const float*)d_in[0];   // (8,2048,256) f32
    const int*   adj = (const int*)d_in[1];     // (8,2048,2048) i32
    const float* W   = (const float*)d_in[2];   // (256,64) f32
    const float* a   = (const float*)d_in[3];   // (128,1) f32
    float* out = (float*)d_out;                 // (8,2048,64) f32

    dim3 wgrid(Bd * Nd / 32, KSPLIT);
    wh_kernel<<<wgrid, 128>>>(h, W);
    wh_combine<<<Bd * Nd * 16 / 256, 256>>>(a);
    dim3 grid(NTILES, Bd, SPLIT);
    gat_kernel<<<grid, 256>>>(adj, out);
}